// round 6
// baseline (speedup 1.0000x reference)
#include <cuda_runtime.h>

// Problem constants (fixed by the dataset)
#define NN      100000      // nodes
#define DIN     256         // input feature dim
#define DOUT    32          // output feature dim
#define RPB     128         // rows per GEMM block
#define GTHREADS 128

// Scratch for pre_sup = x @ W  [NN, DOUT] (12.8 MB, device global per rules)
__device__ float g_presup[(size_t)NN * DOUT];

typedef unsigned long long ull;

__device__ __forceinline__ void ffma2(ull& d, ull a, ull b) {
    asm volatile("fma.rn.f32x2 %0, %1, %2, %0;" : "+l"(d) : "l"(a), "l"(b));
}
__device__ __forceinline__ ull pack2(float x) {
    ull r; asm("mov.b64 %0, {%1, %1};" : "=l"(r) : "f"(x)); return r;
}
__device__ __forceinline__ void unpack2(ull v, float& lo, float& hi) {
    asm("mov.b64 {%0, %1}, %2;" : "=f"(lo), "=f"(hi) : "l"(v));
}

// ---------------------------------------------------------------------------
// Kernel 1: GEMM  pre_sup[N, 32] = x[N, 256] @ W[256, 32]
// 128 threads/block covering 128 rows x 32 cols. Thread tile 4 rows x 8 cols
// as 4x4 packed f32x2 accumulators (FFMA2).
// NO smem staging of x and NO mainloop barriers: W (32 KB) staged to smem
// once; each thread streams its 4 rows straight from GMEM into registers
// with one-group-ahead prefetch (4 independent LDG.128 in flight per warp).
// W reads are 8-way-broadcast LDS.128 (conflict-free).
// ---------------------------------------------------------------------------
__global__ __launch_bounds__(GTHREADS, 6) void gemm_kernel(const float* __restrict__ x,
                                                           const float* __restrict__ w) {
    __shared__ float Ws[DIN * DOUT];     // 32 KB: full W, row-major [k][32]

    const int tid = threadIdx.x;
    // Stage full W: 2048 float4 across 128 threads (16 each)
#pragma unroll
    for (int i = 0; i < 16; i++)
        ((float4*)Ws)[tid + i * GTHREADS] = ((const float4*)w)[tid + i * GTHREADS];
    __syncthreads();                     // only barrier in the kernel

    const int row0  = blockIdx.x * RPB;
    const int tc    = tid & 3;           // -> cols  tc*8 .. tc*8+7
    const int tr    = tid >> 2;          // -> rows  tr*4 .. tr*4+3
    const int rbase = row0 + tr * 4;

    ull acc[4][4];
#pragma unroll
    for (int r = 0; r < 4; r++)
#pragma unroll
        for (int c = 0; c < 4; c++) acc[r][c] = 0ULL;

    if (rbase + 3 < NN) {
        // ---- Fast path: all 4 rows valid ----
        const float* xp = x + (size_t)rbase * DIN;
        float4 xc[4], xn[4];
#pragma unroll
        for (int r = 0; r < 4; r++)
            xc[r] = __ldg((const float4*)(xp + r * DIN));

        for (int k0 = 0; k0 < DIN; k0 += 4) {
            if (k0 + 4 < DIN) {
#pragma unroll
                for (int r = 0; r < 4; r++)
                    xn[r] = __ldg((const float4*)(xp + r * DIN + k0 + 4));
            }
#pragma unroll
            for (int k = 0; k < 4; k++) {
                const float* wrow = Ws + (k0 + k) * DOUT + tc * 8;
                const longlong2 wA = *(const longlong2*)(wrow);
                const longlong2 wB = *(const longlong2*)(wrow + 4);
#pragma unroll
                for (int r = 0; r < 4; r++) {
                    float xs = (k == 0) ? xc[r].x : (k == 1) ? xc[r].y
                             : (k == 2) ? xc[r].z : xc[r].w;
                    ull xv = pack2(xs);
                    ffma2(acc[r][0], xv, (ull)wA.x);
                    ffma2(acc[r][1], xv, (ull)wA.y);
                    ffma2(acc[r][2], xv, (ull)wB.x);
                    ffma2(acc[r][3], xv, (ull)wB.y);
                }
            }
#pragma unroll
            for (int r = 0; r < 4; r++) xc[r] = xn[r];
        }
    } else {
        // ---- Tail path (last block only): per-row guarded scalar loop ----
#pragma unroll 1
        for (int r = 0; r < 4; r++) {
            int grow = rbase + r;
            if (grow >= NN) continue;
            const float* xr = x + (size_t)grow * DIN;
            for (int k = 0; k < DIN; k++) {
                const float* wrow = Ws + k * DOUT + tc * 8;
                ull xv = pack2(xr[k]);
                ffma2(acc[r][0], xv, *(const ull*)(wrow));
                ffma2(acc[r][1], xv, *(const ull*)(wrow + 2));
                ffma2(acc[r][2], xv, *(const ull*)(wrow + 4));
                ffma2(acc[r][3], xv, *(const ull*)(wrow + 6));
            }
        }
    }

    // ---- Epilogue: unpack and store two float4 per row ----
#pragma unroll
    for (int r = 0; r < 4; r++) {
        int grow = rbase + r;
        if (grow < NN) {
            float4 o0, o1;
            unpack2(acc[r][0], o0.x, o0.y);
            unpack2(acc[r][1], o0.z, o0.w);
            unpack2(acc[r][2], o1.x, o1.y);
            unpack2(acc[r][3], o1.z, o1.w);
            float* dst = g_presup + (size_t)grow * DOUT + tc * 8;
            *(float4*)(dst + 0) = o0;
            *(float4*)(dst + 4) = o1;
        }
    }
}

// ---------------------------------------------------------------------------
// Kernel 2: Scatter SpMM  out[row[e]] += val[e] * pre_sup[col[e]]
// 8 threads per edge; one float4 gather + one red.global.add.v4.f32 each.
// ---------------------------------------------------------------------------
__global__ __launch_bounds__(256) void scatter_kernel(const int*   __restrict__ arow,
                                                      const int*   __restrict__ acol,
                                                      const float* __restrict__ aval,
                                                      float*       __restrict__ out,
                                                      int n_edges) {
    long long g = (long long)blockIdx.x * blockDim.x + threadIdx.x;
    int e    = (int)(g >> 3);
    int part = (int)(g & 7);
    if (e >= n_edges) return;

    int   r = arow[e];
    int   c = acol[e];
    float v = aval[e];

    float4 p = *(const float4*)(g_presup + (size_t)c * DOUT + part * 4);
    float m0 = v * p.x, m1 = v * p.y, m2 = v * p.z, m3 = v * p.w;

    float* dst = out + (size_t)r * DOUT + part * 4;
    asm volatile("red.global.add.v4.f32 [%0], {%1, %2, %3, %4};"
                 :: "l"(dst), "f"(m0), "f"(m1), "f"(m2), "f"(m3)
                 : "memory");
}

// ---------------------------------------------------------------------------
// Kernel 3: in-place ReLU on out
// ---------------------------------------------------------------------------
__global__ __launch_bounds__(256) void relu_kernel(float* __restrict__ out, int n4) {
    int i = blockIdx.x * blockDim.x + threadIdx.x;
    if (i < n4) {
        float4 v = ((float4*)out)[i];
        v.x = fmaxf(v.x, 0.f);
        v.y = fmaxf(v.y, 0.f);
        v.z = fmaxf(v.z, 0.f);
        v.w = fmaxf(v.w, 0.f);
        ((float4*)out)[i] = v;
    }
}

// ---------------------------------------------------------------------------
// kernel_launch: memset(out) -> gemm -> scatter -> relu
// ---------------------------------------------------------------------------
extern "C" void kernel_launch(void* const* d_in, const int* in_sizes, int n_in,
                              void* d_out, int out_size) {
    const float* x    = (const float*)d_in[0];
    const int*   arow = (const int*)  d_in[1];
    const int*   acol = (const int*)  d_in[2];
    const float* aval = (const float*)d_in[3];
    const float* w    = (const float*)d_in[4];
    float*       out  = (float*)d_out;

    const int n_edges = in_sizes[1];

    cudaMemsetAsync(out, 0, (size_t)out_size * sizeof(float), 0);

    gemm_kernel<<<(NN + RPB - 1) / RPB, GTHREADS>>>(x, w);

    long long sthreads = (long long)n_edges * 8;
    int sblocks = (int)((sthreads + 255) / 256);
    scatter_kernel<<<sblocks, 256>>>(arow, acol, aval, out, n_edges);

    int n4 = out_size / 4;
    relu_kernel<<<(n4 + 255) / 256, 256>>>(out, n4);
}

// round 7
// speedup vs baseline: 1.3179x; 1.3179x over previous
#include <cuda_runtime.h>
#include <cstdint>

// Problem constants (fixed by the dataset)
#define NN      100000      // nodes
#define DIN     256         // input feature dim
#define DOUT    32          // output feature dim
#define GTHREADS 256        // 8 warps
#define RPW     16          // rows per warp (m16)
#define RPB     (RPW * 8)   // 128 rows per block
#define NKS     (DIN / 8)   // 32 k-steps of k8

// Scratch for pre_sup = x @ W  [NN, DOUT] (12.8 MB, device global per rules)
__device__ float g_presup[(size_t)NN * DOUT];

__device__ __forceinline__ uint32_t f2tf32(float f) {
    uint32_t u;
    asm("cvt.rna.tf32.f32 %0, %1;" : "=r"(u) : "f"(f));
    return u;
}

__device__ __forceinline__ void mma_tf32(float4& d,
                                         uint32_t a0, uint32_t a1, uint32_t a2, uint32_t a3,
                                         uint32_t b0, uint32_t b1) {
    asm volatile("mma.sync.aligned.m16n8k8.row.col.f32.tf32.tf32.f32 "
                 "{%0,%1,%2,%3}, {%4,%5,%6,%7}, {%8,%9}, {%0,%1,%2,%3};"
                 : "+f"(d.x), "+f"(d.y), "+f"(d.z), "+f"(d.w)
                 : "r"(a0), "r"(a1), "r"(a2), "r"(a3), "r"(b0), "r"(b1));
}

// ---------------------------------------------------------------------------
// Kernel 1: GEMM  pre_sup[N, 32] = x[N, 256] @ W[256, 32]  via tf32 mma.sync.
// 8 warps/block, each warp owns 16 rows (m16), full N=32 as 4 n8 blocks,
// K=256 as 32 k8 steps. B fragments for the whole W precomputed to smem in
// per-lane fragment order (one conflict-free LDS.64 per mma). A fragments
// stream directly from GMEM (4 LDG.32 per k-step, a0/a2 fill 32B sectors).
// One __syncthreads total.
// ---------------------------------------------------------------------------
__global__ __launch_bounds__(GTHREADS, 4) void gemm_kernel(const float* __restrict__ x,
                                                           const float* __restrict__ w) {
    // Bfrag[(ks*4 + nb)*32 + lane] = {b0, b1} (tf32 bits), 32 KB
    __shared__ uint2 Bfrag[NKS * 4 * 32];

    const int tid = threadIdx.x;

    // ---- Build B fragments: each of 4096 (ks, nb, lane) entries once ----
    for (int i = tid; i < NKS * 4 * 32; i += GTHREADS) {
        int ks  = i >> 7;           // /128
        int rem = i & 127;
        int nb  = rem >> 5;
        int ln  = rem & 31;
        int t = ln & 3, g = ln >> 2;
        // mma row.col B fragment: b0 = B[k = t][n = g], b1 = B[k = t+4][n = g]
        float w0 = w[(ks * 8 + t)     * DOUT + nb * 8 + g];
        float w1 = w[(ks * 8 + t + 4) * DOUT + nb * 8 + g];
        Bfrag[i] = make_uint2(f2tf32(w0), f2tf32(w1));
    }
    __syncthreads();

    const int wid  = tid >> 5;
    const int lane = tid & 31;
    const int t    = lane & 3;      // threadID in group
    const int g    = lane >> 2;     // groupID
    const int rw   = blockIdx.x * RPB + wid * RPW;
    const int r0   = rw + g;        // rows g and g+8 of the m16 tile
    const int r1   = rw + g + 8;
    // Clamp load rows (OOB rows compute garbage, discarded at store)
    const int r0c  = (r0 < NN) ? r0 : (NN - 1);
    const int r1c  = (r1 < NN) ? r1 : (NN - 1);

    const float* xa = x + (size_t)r0c * DIN + t;
    const float* xb = x + (size_t)r1c * DIN + t;

    float4 acc[4];
#pragma unroll
    for (int nb = 0; nb < 4; nb++) acc[nb] = make_float4(0.f, 0.f, 0.f, 0.f);

#pragma unroll 8
    for (int ks = 0; ks < NKS; ks++) {
        const int k0 = ks * 8;
        // A fragment (row-major): a0=(g,t) a1=(g+8,t) a2=(g,t+4) a3=(g+8,t+4)
        uint32_t a0 = f2tf32(__ldg(xa + k0));
        uint32_t a1 = f2tf32(__ldg(xb + k0));
        uint32_t a2 = f2tf32(__ldg(xa + k0 + 4));
        uint32_t a3 = f2tf32(__ldg(xb + k0 + 4));

        const uint2* bp = Bfrag + ks * 4 * 32 + lane;
        uint2 b0 = bp[0 * 32];
        uint2 b1 = bp[1 * 32];
        uint2 b2 = bp[2 * 32];
        uint2 b3 = bp[3 * 32];
        mma_tf32(acc[0], a0, a1, a2, a3, b0.x, b0.y);
        mma_tf32(acc[1], a0, a1, a2, a3, b1.x, b1.y);
        mma_tf32(acc[2], a0, a1, a2, a3, b2.x, b2.y);
        mma_tf32(acc[3], a0, a1, a2, a3, b3.x, b3.y);
    }

    // ---- Epilogue: D fragment c0,c1 -> row g cols (2t, 2t+1); c2,c3 -> row g+8
#pragma unroll
    for (int nb = 0; nb < 4; nb++) {
        if (r0 < NN)
            *(float2*)(g_presup + (size_t)r0 * DOUT + nb * 8 + 2 * t) =
                make_float2(acc[nb].x, acc[nb].y);
        if (r1 < NN)
            *(float2*)(g_presup + (size_t)r1 * DOUT + nb * 8 + 2 * t) =
                make_float2(acc[nb].z, acc[nb].w);
    }
}

// ---------------------------------------------------------------------------
// Kernel 2: Scatter SpMM  out[row[e]] += val[e] * pre_sup[col[e]]
// 8 threads per edge; one float4 gather + one red.global.add.v4.f32 each.
// ---------------------------------------------------------------------------
__global__ __launch_bounds__(256) void scatter_kernel(const int*   __restrict__ arow,
                                                      const int*   __restrict__ acol,
                                                      const float* __restrict__ aval,
                                                      float*       __restrict__ out,
                                                      int n_edges) {
    long long gdx = (long long)blockIdx.x * blockDim.x + threadIdx.x;
    int e    = (int)(gdx >> 3);
    int part = (int)(gdx & 7);
    if (e >= n_edges) return;

    int   r = arow[e];
    int   c = acol[e];
    float v = aval[e];

    float4 p = *(const float4*)(g_presup + (size_t)c * DOUT + part * 4);
    float m0 = v * p.x, m1 = v * p.y, m2 = v * p.z, m3 = v * p.w;

    float* dst = out + (size_t)r * DOUT + part * 4;
    asm volatile("red.global.add.v4.f32 [%0], {%1, %2, %3, %4};"
                 :: "l"(dst), "f"(m0), "f"(m1), "f"(m2), "f"(m3)
                 : "memory");
}

// ---------------------------------------------------------------------------
// Kernel 3: in-place ReLU on out
// ---------------------------------------------------------------------------
__global__ __launch_bounds__(256) void relu_kernel(float* __restrict__ out, int n4) {
    int i = blockIdx.x * blockDim.x + threadIdx.x;
    if (i < n4) {
        float4 v = ((float4*)out)[i];
        v.x = fmaxf(v.x, 0.f);
        v.y = fmaxf(v.y, 0.f);
        v.z = fmaxf(v.z, 0.f);
        v.w = fmaxf(v.w, 0.f);
        ((float4*)out)[i] = v;
    }
}

// ---------------------------------------------------------------------------
// kernel_launch: memset(out) -> gemm -> scatter -> relu
// ---------------------------------------------------------------------------
extern "C" void kernel_launch(void* const* d_in, const int* in_sizes, int n_in,
                              void* d_out, int out_size) {
    const float* x    = (const float*)d_in[0];
    const int*   arow = (const int*)  d_in[1];
    const int*   acol = (const int*)  d_in[2];
    const float* aval = (const float*)d_in[3];
    const float* w    = (const float*)d_in[4];
    float*       out  = (float*)d_out;

    const int n_edges = in_sizes[1];

    cudaMemsetAsync(out, 0, (size_t)out_size * sizeof(float), 0);

    gemm_kernel<<<(NN + RPB - 1) / RPB, GTHREADS>>>(x, w);

    long long sthreads = (long long)n_edges * 8;
    int sblocks = (int)((sthreads + 255) / 256);
    scatter_kernel<<<sblocks, 256>>>(arow, acol, aval, out, n_edges);

    int n4 = out_size / 4;
    relu_kernel<<<(n4 + 255) / 256, 256>>>(out, n4);
}

// round 8
// speedup vs baseline: 1.4154x; 1.0740x over previous
#include <cuda_runtime.h>
#include <cstdint>

// Problem constants (fixed by the dataset)
#define NN      100000      // nodes
#define DIN     256         // input feature dim
#define DOUT    32          // output feature dim
#define GTHREADS 256        // 8 warps
#define RPW     16          // rows per warp (m16)
#define RPB     (RPW * 8)   // 128 rows per block
#define NKS     (DIN / 8)   // 32 k-steps of k8
#define CHUNK_COLS 32       // k-columns per pipeline chunk
#define KSPC    4           // k-steps per chunk
#define NCHUNK  (DIN / CHUNK_COLS)   // 8
#define XS_STRIDE 36        // floats per staged row (144B, 16B-aligned, bank-spread)
#define XBUF_FLOATS (RPB * XS_STRIDE)
#define BFRAG_BYTES (NKS * 4 * 32 * 8)          // 32 KB
#define SMEM_BYTES  (BFRAG_BYTES + 2 * XBUF_FLOATS * 4)

// Scratch for pre_sup = x @ W  [NN, DOUT] (12.8 MB, device global per rules)
__device__ float g_presup[(size_t)NN * DOUT];

__device__ __forceinline__ uint32_t f2tf32(float f) {
    uint32_t u;
    asm("cvt.rna.tf32.f32 %0, %1;" : "=r"(u) : "f"(f));
    return u;
}

__device__ __forceinline__ void mma_tf32(float4& d,
                                         uint32_t a0, uint32_t a1, uint32_t a2, uint32_t a3,
                                         uint32_t b0, uint32_t b1) {
    asm volatile("mma.sync.aligned.m16n8k8.row.col.f32.tf32.tf32.f32 "
                 "{%0,%1,%2,%3}, {%4,%5,%6,%7}, {%8,%9}, {%0,%1,%2,%3};"
                 : "+f"(d.x), "+f"(d.y), "+f"(d.z), "+f"(d.w)
                 : "r"(a0), "r"(a1), "r"(a2), "r"(a3), "r"(b0), "r"(b1));
}

__device__ __forceinline__ uint32_t smem_u32(const void* p) {
    uint32_t a;
    asm("{ .reg .u64 t; cvta.to.shared.u64 t, %1; cvt.u32.u64 %0, t; }"
        : "=r"(a) : "l"(p));
    return a;
}

__device__ __forceinline__ void cp_async16(uint32_t dst, const void* src, int nbytes) {
    asm volatile("cp.async.ca.shared.global [%0], [%1], 16, %2;"
                 :: "r"(dst), "l"(src), "r"(nbytes) : "memory");
}

// Issue cp.async for one 32-col chunk of the block's 128-row X tile.
__device__ __forceinline__ void issue_chunk(uint32_t xs_addr, const float* __restrict__ x,
                                            int row0, int kc, int tid) {
#pragma unroll
    for (int j = 0; j < 4; j++) {
        int i    = tid + j * GTHREADS;      // 0..1023
        int r    = i >> 3;                  // staged row 0..127
        int seg  = i & 7;                   // 16B segment within 32 cols
        int grow = row0 + r;
        int gsrc = (grow < NN) ? grow : (NN - 1);   // clamp (zfill anyway)
        const float* src = x + (size_t)gsrc * DIN + kc + seg * 4;
        uint32_t dst = xs_addr + (uint32_t)(r * (XS_STRIDE * 4) + seg * 16);
        cp_async16(dst, src, (grow < NN) ? 16 : 0);
    }
    asm volatile("cp.async.commit_group;" ::: "memory");
}

// ---------------------------------------------------------------------------
// Kernel 1: GEMM  pre_sup[N, 32] = x[N, 256] @ W[256, 32]  via tf32 mma.sync.
// 8 warps/block, warp owns 16 rows; N=32 as 4 n8 blocks; K=256 as 32 k8.
// B fragments precomputed to smem (conflict-free LDS.64 per mma).
// X tile cp.async-staged in 8 chunks of 32 cols, double-buffered (depth-2
// commit groups). Staged rows use stride 36 floats so fragment LDS.32 reads
// hit 32 distinct banks (bank = 4g + t): 1 wavefront each.
// ---------------------------------------------------------------------------
__global__ __launch_bounds__(GTHREADS, 3) void gemm_kernel(const float* __restrict__ x,
                                                           const float* __restrict__ w) {
    extern __shared__ char smem[];
    uint2* Bfrag = (uint2*)smem;                         // 32 KB
    float* Xbuf  = (float*)(smem + BFRAG_BYTES);         // 2 x 18 KB
    const uint32_t xb_addr0 = smem_u32(Xbuf);
    const uint32_t xb_addr1 = xb_addr0 + XBUF_FLOATS * 4;

    const int tid  = threadIdx.x;
    const int row0 = blockIdx.x * RPB;

    // ---- Start the async pipeline immediately: chunks 0 and 1 ----
    issue_chunk(xb_addr0, x, row0, 0,          tid);
    issue_chunk(xb_addr1, x, row0, CHUNK_COLS, tid);

    // ---- Build B fragments (overlaps with in-flight cp.async) ----
    for (int i = tid; i < NKS * 4 * 32; i += GTHREADS) {
        int ks  = i >> 7;
        int rem = i & 127;
        int nb  = rem >> 5;
        int ln  = rem & 31;
        int t = ln & 3, g = ln >> 2;
        float w0 = w[(ks * 8 + t)     * DOUT + nb * 8 + g];
        float w1 = w[(ks * 8 + t + 4) * DOUT + nb * 8 + g];
        Bfrag[i] = make_uint2(f2tf32(w0), f2tf32(w1));
    }

    const int wid  = tid >> 5;
    const int lane = tid & 31;
    const int t    = lane & 3;
    const int g    = lane >> 2;
    const int rl   = wid * RPW;          // warp's first local row

    float4 acc[4];
#pragma unroll
    for (int nb = 0; nb < 4; nb++) acc[nb] = make_float4(0.f, 0.f, 0.f, 0.f);

    // Fragment LDS base offsets (floats) within a buffer
    const int offA = (rl + g) * XS_STRIDE + t;           // a0/a2 row
    const int offB = (rl + g + 8) * XS_STRIDE + t;       // a1/a3 row

#pragma unroll
    for (int c = 0; c < NCHUNK; c++) {
        if (c < NCHUNK - 1)
            asm volatile("cp.async.wait_group 1;" ::: "memory");
        else
            asm volatile("cp.async.wait_group 0;" ::: "memory");
        __syncthreads();                 // chunk c resident (and Bfrag on c==0)

        const float* Xs = Xbuf + (c & 1) * XBUF_FLOATS;
#pragma unroll
        for (int ksl = 0; ksl < KSPC; ksl++) {
            const int k0 = ksl * 8;
            uint32_t a0 = f2tf32(Xs[offA + k0]);
            uint32_t a1 = f2tf32(Xs[offB + k0]);
            uint32_t a2 = f2tf32(Xs[offA + k0 + 4]);
            uint32_t a3 = f2tf32(Xs[offB + k0 + 4]);

            const uint2* bp = Bfrag + (c * KSPC + ksl) * 4 * 32 + lane;
            uint2 b0 = bp[0 * 32];
            uint2 b1 = bp[1 * 32];
            uint2 b2 = bp[2 * 32];
            uint2 b3 = bp[3 * 32];
            mma_tf32(acc[0], a0, a1, a2, a3, b0.x, b0.y);
            mma_tf32(acc[1], a0, a1, a2, a3, b1.x, b1.y);
            mma_tf32(acc[2], a0, a1, a2, a3, b2.x, b2.y);
            mma_tf32(acc[3], a0, a1, a2, a3, b3.x, b3.y);
        }

        if (c + 2 < NCHUNK) {
            __syncthreads();             // everyone done reading buf (c&1)
            issue_chunk((c & 1) ? xb_addr1 : xb_addr0, x, row0,
                        (c + 2) * CHUNK_COLS, tid);
        }
    }

    // ---- Epilogue: c0,c1 -> row g cols (2t,2t+1); c2,c3 -> row g+8 ----
    const int r0 = row0 + rl + g;
    const int r1 = row0 + rl + g + 8;
#pragma unroll
    for (int nb = 0; nb < 4; nb++) {
        if (r0 < NN)
            *(float2*)(g_presup + (size_t)r0 * DOUT + nb * 8 + 2 * t) =
                make_float2(acc[nb].x, acc[nb].y);
        if (r1 < NN)
            *(float2*)(g_presup + (size_t)r1 * DOUT + nb * 8 + 2 * t) =
                make_float2(acc[nb].z, acc[nb].w);
    }
}

// ---------------------------------------------------------------------------
// Kernel 2: Scatter SpMM  out[row[e]] += val[e] * pre_sup[col[e]]
// 8 threads per edge; one float4 gather + one red.global.add.v4.f32 each.
// ---------------------------------------------------------------------------
__global__ __launch_bounds__(256) void scatter_kernel(const int*   __restrict__ arow,
                                                      const int*   __restrict__ acol,
                                                      const float* __restrict__ aval,
                                                      float*       __restrict__ out,
                                                      int n_edges) {
    long long gdx = (long long)blockIdx.x * blockDim.x + threadIdx.x;
    int e    = (int)(gdx >> 3);
    int part = (int)(gdx & 7);
    if (e >= n_edges) return;

    int   r = arow[e];
    int   c = acol[e];
    float v = aval[e];

    float4 p = *(const float4*)(g_presup + (size_t)c * DOUT + part * 4);
    float m0 = v * p.x, m1 = v * p.y, m2 = v * p.z, m3 = v * p.w;

    float* dst = out + (size_t)r * DOUT + part * 4;
    asm volatile("red.global.add.v4.f32 [%0], {%1, %2, %3, %4};"
                 :: "l"(dst), "f"(m0), "f"(m1), "f"(m2), "f"(m3)
                 : "memory");
}

// ---------------------------------------------------------------------------
// Kernel 3: in-place ReLU on out
// ---------------------------------------------------------------------------
__global__ __launch_bounds__(256) void relu_kernel(float* __restrict__ out, int n4) {
    int i = blockIdx.x * blockDim.x + threadIdx.x;
    if (i < n4) {
        float4 v = ((float4*)out)[i];
        v.x = fmaxf(v.x, 0.f);
        v.y = fmaxf(v.y, 0.f);
        v.z = fmaxf(v.z, 0.f);
        v.w = fmaxf(v.w, 0.f);
        ((float4*)out)[i] = v;
    }
}

// ---------------------------------------------------------------------------
// kernel_launch: memset(out) -> gemm -> scatter -> relu
// ---------------------------------------------------------------------------
extern "C" void kernel_launch(void* const* d_in, const int* in_sizes, int n_in,
                              void* d_out, int out_size) {
    const float* x    = (const float*)d_in[0];
    const int*   arow = (const int*)  d_in[1];
    const int*   acol = (const int*)  d_in[2];
    const float* aval = (const float*)d_in[3];
    const float* w    = (const float*)d_in[4];
    float*       out  = (float*)d_out;

    const int n_edges = in_sizes[1];

    // Idempotent (not a stream op -> capture-safe)
    cudaFuncSetAttribute(gemm_kernel, cudaFuncAttributeMaxDynamicSharedMemorySize,
                         SMEM_BYTES);

    cudaMemsetAsync(out, 0, (size_t)out_size * sizeof(float), 0);

    gemm_kernel<<<(NN + RPB - 1) / RPB, GTHREADS, SMEM_BYTES>>>(x, w);

    long long sthreads = (long long)n_edges * 8;
    int sblocks = (int)((sthreads + 255) / 256);
    scatter_kernel<<<sblocks, 256>>>(arow, acol, aval, out, n_edges);

    int n4 = out_size / 4;
    relu_kernel<<<(n4 + 255) / 256, 256>>>(out, n4);
}